// round 4
// baseline (speedup 1.0000x reference)
#include <cuda_runtime.h>

#define SDIM 8192
#define CIN  32
#define COUT 8
#define BDIM 128
#define STILE 32
#define NTHREADS 256
#define BG 4                 // b-groups (blocks along batch)
#define BPB (BDIM / BG)      // 32 b per block
#define BPT (BPB / 8)        // 4 b per thread

// 1 MB device scratch for the w1 column-sum (no allocation — static global)
__device__ float g_wsum[CIN * SDIM];

__device__ __forceinline__ float ftanh(float v) {
    float e = __expf(2.0f * v);
    return 1.0f - __fdividef(2.0f, e + 1.0f);
}

// ---- Kernel A: wsum[j][s] = sum_i w1[i][j][s] (w1 read exactly once) ----
__global__ __launch_bounds__(256)
void wsum_kernel(const float* __restrict__ w1) {
    int idx = blockIdx.x * 256 + threadIdx.x;   // idx = j*SDIM + s, coalesced
    float acc = 0.0f;
    #pragma unroll
    for (int i = 0; i < CIN; i++)
        acc += w1[i * (CIN * SDIM) + idx];
    g_wsum[idx] = acc;
}

// ---- Kernel B: fused tanh-scale + contraction + bias + tanh ----
__global__ __launch_bounds__(NTHREADS, 3)
void lc3_main_kernel(const float* __restrict__ x,
                     const float* __restrict__ w2,
                     const float* __restrict__ bias,
                     float* __restrict__ out) {
    __shared__ float s_w2[CIN * COUT * STILE];   // 32 KB, [(j*8+o)*32+sl]
    __shared__ float s_ws[CIN * STILE];          // 4 KB,  [j*32+sl]

    const int tid = threadIdx.x;
    const int sl  = tid & 31;
    const int bt  = tid >> 5;
    const int s0  = blockIdx.x * STILE;
    const int sg  = s0 + sl;
    const int bb  = blockIdx.y * BPB;            // this block's first b

    // Stage w2 slice (coalesced; re-read BG times across b-groups — cheap)
    #pragma unroll
    for (int p = 0; p < (CIN * COUT * STILE) / NTHREADS; p++) {
        int lin = p * NTHREADS + tid;            // = (j*8+o)*32 + sl2
        int jo  = lin >> 5;
        int sl2 = lin & 31;
        int j   = jo >> 3;
        int o   = jo & 7;
        s_w2[lin] = w2[(o * CIN + j) * SDIM + s0 + sl2];
    }

    // Stage wsum tile from global scratch (L2-resident after first touch)
    #pragma unroll
    for (int p = 0; p < (CIN * STILE) / NTHREADS; p++) {
        int lin = p * NTHREADS + tid;            // = j*32 + sl2
        int j   = lin >> 5;
        int sl2 = lin & 31;
        s_ws[lin] = g_wsum[j * SDIM + s0 + sl2];
    }

    float bia[COUT];
    #pragma unroll
    for (int o = 0; o < COUT; o++)
        bia[o] = bias[o * SDIM + sg];

    __syncthreads();

    #pragma unroll
    for (int ib = 0; ib < BPT; ib++) {
        const int b = bb + bt * BPT + ib;
        const float* xp = x + (b * CIN) * SDIM + sg;

        float a[COUT];
        #pragma unroll
        for (int o = 0; o < COUT; o++) a[o] = bia[o];

        // j in two chunks of 16: 16 batched LDGs, then MUFU+FMA burst
        #pragma unroll
        for (int jc = 0; jc < 2; jc++) {
            float xv[16];
            #pragma unroll
            for (int jj = 0; jj < 16; jj++)
                xv[jj] = xp[(jc * 16 + jj) * SDIM];

            #pragma unroll
            for (int jj = 0; jj < 16; jj++) {
                int j = jc * 16 + jj;
                float h = ftanh(xv[jj] * s_ws[j * 32 + sl]);
                #pragma unroll
                for (int o = 0; o < COUT; o++)
                    a[o] = fmaf(h, s_w2[(j * 8 + o) * 32 + sl], a[o]);
            }
        }

        float* op = out + (b * COUT) * SDIM + sg;
        #pragma unroll
        for (int o = 0; o < COUT; o++)
            op[o * SDIM] = ftanh(a[o]);
    }
}

extern "C" void kernel_launch(void* const* d_in, const int* in_sizes, int n_in,
                              void* d_out, int out_size) {
    const float* x    = (const float*)d_in[0];
    const float* w1   = (const float*)d_in[1];
    const float* w2   = (const float*)d_in[2];
    const float* bias = (const float*)d_in[3];
    float* out = (float*)d_out;

    wsum_kernel<<<(CIN * SDIM) / 256, 256>>>(w1);

    dim3 grid(SDIM / STILE, BG);   // 256 x 4 = 1024 blocks
    lc3_main_kernel<<<grid, NTHREADS>>>(x, w2, bias, out);
}

// round 6
// speedup vs baseline: 3.2088x; 3.2088x over previous
#include <cuda_runtime.h>

#define SDIM 8192
#define CIN  32
#define COUT 8
#define BDIM 128
#define STILE 128            // s per block (32 lanes x float4)
#define SQ    (STILE / 4)    // 32 float4 per row
#define NTHREADS 512         // 16 warps, one b each
#define BG 8                 // b-groups
#define BPB (BDIM / BG)      // 16 b per block

// w1 column-sum scratch (static device global — no allocation)
__device__ float g_wsum[CIN * SDIM];

// dynamic smem: w2 tile, float4 layout [(j*8+o)*SQ + q]
#define SMEM_BYTES (CIN * COUT * STILE * 4)

__device__ __forceinline__ float ftanh(float v) {
    float e = __expf(2.0f * v);
    return 1.0f - __fdividef(2.0f, e + 1.0f);
}

// ---- Kernel A: wsum[j][s] = sum_i w1[i][j][s] ----
__global__ __launch_bounds__(256)
void wsum_kernel(const float* __restrict__ w1) {
    int idx = blockIdx.x * 256 + threadIdx.x;
    float acc = 0.0f;
    #pragma unroll
    for (int i = 0; i < CIN; i++)
        acc += w1[i * (CIN * SDIM) + idx];
    g_wsum[idx] = acc;
}

// ---- Kernel B: fused main ----
__global__ __launch_bounds__(NTHREADS, 1)
void lc3_main_kernel(const float* __restrict__ x,
                     const float* __restrict__ w2,
                     const float* __restrict__ bias,
                     float* __restrict__ out) {
    extern __shared__ float4 s_w2[];   // [CIN*COUT*SQ] float4 = 128 KB

    const int tid  = threadIdx.x;
    const int lane = tid & 31;
    const int wi   = tid >> 5;                 // warp 0..15 -> b index
    const int s0   = blockIdx.y * STILE;       // s tile (grid.y)
    const int bb   = blockIdx.x * BPB;         // b group  (grid.x fastest -> L2 share)
    const int b    = bb + wi;

    // Stage w2 tile: CIN*COUT*SQ = 32*8*32 = 8192 float4 elems
    // gmem source for lin=(j*8+o)*SQ+q : w2[(o*CIN+j)*SDIM + s0 + q*4]
    #pragma unroll
    for (int p = 0; p < (CIN * COUT * SQ) / NTHREADS; p++) {
        int lin = p * NTHREADS + tid;
        int q   = lin & (SQ - 1);
        int jo  = lin / SQ;
        int j   = jo >> 3;
        int o   = jo & 7;
        s_w2[lin] = *(const float4*)(w2 + (o * CIN + j) * SDIM + s0 + q * 4);
    }
    __syncthreads();

    // Accumulators init from bias (float4 per o; bias tile L1-resident across warps)
    float4 acc[COUT];
    #pragma unroll
    for (int o = 0; o < COUT; o++)
        acc[o] = *(const float4*)(bias + o * SDIM + s0 + lane * 4);

    const float* xp = x + (b * CIN) * SDIM + s0 + lane * 4;
    const float* wp = g_wsum + s0 + lane * 4;

    // j in chunks of 4: 8 float4 LDGs in flight (x + wsum), then compute burst
    #pragma unroll
    for (int jc = 0; jc < CIN / 4; jc++) {
        float4 xv[4], wv[4];
        #pragma unroll
        for (int jj = 0; jj < 4; jj++) {
            int j = jc * 4 + jj;
            xv[jj] = *(const float4*)(xp + j * SDIM);
            wv[jj] = *(const float4*)(wp + j * SDIM);
        }
        #pragma unroll
        for (int jj = 0; jj < 4; jj++) {
            int j = jc * 4 + jj;
            float4 h;
            h.x = ftanh(xv[jj].x * wv[jj].x);
            h.y = ftanh(xv[jj].y * wv[jj].y);
            h.z = ftanh(xv[jj].z * wv[jj].z);
            h.w = ftanh(xv[jj].w * wv[jj].w);
            #pragma unroll
            for (int o = 0; o < COUT; o++) {
                float4 w = s_w2[(j * 8 + o) * SQ + lane];
                acc[o].x = fmaf(h.x, w.x, acc[o].x);
                acc[o].y = fmaf(h.y, w.y, acc[o].y);
                acc[o].z = fmaf(h.z, w.z, acc[o].z);
                acc[o].w = fmaf(h.w, w.w, acc[o].w);
            }
        }
    }

    // Output: tanh + float4 stores (512B per warp-store)
    float* op = out + (b * COUT) * SDIM + s0 + lane * 4;
    #pragma unroll
    for (int o = 0; o < COUT; o++) {
        float4 r;
        r.x = ftanh(acc[o].x);
        r.y = ftanh(acc[o].y);
        r.z = ftanh(acc[o].z);
        r.w = ftanh(acc[o].w);
        *(float4*)(op + o * SDIM) = r;
    }
}

extern "C" void kernel_launch(void* const* d_in, const int* in_sizes, int n_in,
                              void* d_out, int out_size) {
    const float* x    = (const float*)d_in[0];
    const float* w1   = (const float*)d_in[1];
    const float* w2   = (const float*)d_in[2];
    const float* bias = (const float*)d_in[3];
    float* out = (float*)d_out;

    // Host-side attribute set: not a stream op, capture-safe; persists after
    // the first (uncaptured) correctness call.
    cudaFuncSetAttribute(lc3_main_kernel,
                         cudaFuncAttributeMaxDynamicSharedMemorySize, SMEM_BYTES);

    wsum_kernel<<<(CIN * SDIM) / 256, 256>>>(w1);

    dim3 grid(BG, SDIM / STILE);   // (8, 64) — b-group fastest for L2 tile sharing
    lc3_main_kernel<<<grid, NTHREADS, SMEM_BYTES>>>(x, w2, bias, out);
}